// round 1
// baseline (speedup 1.0000x reference)
#include <cuda_runtime.h>
#include <math.h>

#define FR 16
#define NV 4096
#define NT 512
#define MP 4096
#define SCALE 0.1f

// Per-frame fused transform: c_j = sum_k p_k * A[f][k*3+j] + B[f][j]
__device__ float g_A[FR][9];
__device__ float g_B[FR][3];

__device__ __forceinline__ void rot_from_omega(const float* om, float dtv, float* R) {
    float th = sqrtf(om[0]*om[0] + om[1]*om[1] + om[2]*om[2]);
    float inv = 1.0f / fmaxf(th, 1e-8f);
    float ax = om[0]*inv, ay = om[1]*inv, az = om[2]*inv;
    float s = sinf(th * dtv);
    float c = 1.0f - cosf(th * dtv);
    float S[9] = {0.f, -az, ay,  az, 0.f, -ax,  -ay, ax, 0.f};
    float S2[9];
    for (int i = 0; i < 3; i++)
        for (int j = 0; j < 3; j++) {
            float v = 0.f;
            for (int k = 0; k < 3; k++) v += S[i*3+k] * S[k*3+j];
            S2[i*3+j] = v;
        }
    for (int i = 0; i < 9; i++) {
        float eye = (i == 0 || i == 4 || i == 8) ? 1.0f : 0.0f;
        R[i] = eye + s * S[i] + c * S2[i];
    }
}

__global__ void pose_kernel(const float* __restrict__ state,
                            const float* __restrict__ pps,
                            const float* __restrict__ dt,
                            float* __restrict__ out) {
    if (threadIdx.x != 0 || blockIdx.x != 0) return;
    out[0] = 0.0f;

    float t[3] = {state[0], state[1], state[2]};
    float r[9];
    rot_from_omega(state + 3, 1.0f, r);

    const float invS = 1.0f / SCALE;
    for (int f = 0; f < FR; f++) {
        if (f > 0) {
            const float* row = pps + f * 12;
            float d = dt[f];
            t[0] += row[6] * d;
            t[1] += row[7] * d;
            t[2] += row[8] * d;
            float Rn[9];
            rot_from_omega(row + 9, d, Rn);
            float rNew[9];
            for (int i = 0; i < 3; i++)
                for (int j = 0; j < 3; j++) {
                    float v = 0.f;
                    for (int k = 0; k < 3; k++) v += Rn[i*3+k] * r[k*3+j];
                    rNew[i*3+j] = v;
                }
            for (int i = 0; i < 9; i++) r[i] = rNew[i];
        }
        // store fused transform for frame f
        for (int i = 0; i < 9; i++) g_A[f][i] = r[i] * invS;
        for (int j = 0; j < 3; j++) {
            float v = t[0]*r[0*3+j] + t[1]*r[1*3+j] + t[2]*r[2*3+j];
            g_B[f][j] = -v * invS;
        }
    }
}

__global__ void __launch_bounds__(256)
chamfer_kernel(const float* __restrict__ model,
               const float* __restrict__ vis,
               const float* __restrict__ tac,
               float* __restrict__ out) {
    extern __shared__ float4 sm[];   // MP entries: (x, y, z, |g|^2)

    // Stage model points into shared memory
    for (int i = threadIdx.x; i < MP; i += blockDim.x) {
        float x = model[3*i], y = model[3*i+1], z = model[3*i+2];
        sm[i] = make_float4(x, y, z, x*x + y*y + z*z);
    }
    __syncthreads();

    const int idx = blockIdx.x * blockDim.x + threadIdx.x;
    const int total = FR * NV + FR * NT;

    float contrib = 0.0f;
    if (idx < total) {
        int f;
        const float* p;
        float w;
        if (idx < FR * NV) {
            f = idx >> 12;               // /NV
            p = vis + 3 * idx;
            w = 1.0f / (float)NV;
        } else {
            int j = idx - FR * NV;
            f = j >> 9;                  // /NT
            p = tac + 3 * j;
            w = 0.1f / (float)NT;
        }

        float px = p[0], py = p[1], pz = p[2];
        const float* A = g_A[f];
        const float* B = g_B[f];
        float cx = fmaf(px, A[0], fmaf(py, A[3], fmaf(pz, A[6], B[0])));
        float cy = fmaf(px, A[1], fmaf(py, A[4], fmaf(pz, A[7], B[1])));
        float cz = fmaf(px, A[2], fmaf(py, A[5], fmaf(pz, A[8], B[2])));

        float pn = cx*cx + cy*cy + cz*cz;
        float mx = -2.0f * cx, my = -2.0f * cy, mz = -2.0f * cz;

        float best = INFINITY;
        #pragma unroll 8
        for (int jm = 0; jm < MP; jm++) {
            float4 g = sm[jm];
            float d = fmaf(mx, g.x, fmaf(my, g.y, fmaf(mz, g.z, g.w)));
            best = fminf(best, d);
        }
        contrib = (pn + best) * w;
    }

    // Block reduction: warp shuffle, then cross-warp via smem, one atomic per block
    __shared__ float warp_sums[8];
    unsigned mask = 0xFFFFFFFFu;
    #pragma unroll
    for (int off = 16; off > 0; off >>= 1)
        contrib += __shfl_down_sync(mask, contrib, off);

    int lane = threadIdx.x & 31;
    int wid  = threadIdx.x >> 5;
    if (lane == 0) warp_sums[wid] = contrib;
    __syncthreads();
    if (wid == 0) {
        float v = (lane < 8) ? warp_sums[lane] : 0.0f;
        #pragma unroll
        for (int off = 4; off > 0; off >>= 1)
            v += __shfl_down_sync(mask, v, off);
        if (lane == 0) atomicAdd(out, v);
    }
}

extern "C" void kernel_launch(void* const* d_in, const int* in_sizes, int n_in,
                              void* d_out, int out_size) {
    const float* state = (const float*)d_in[0];
    const float* model = (const float*)d_in[1];
    const float* vis   = (const float*)d_in[2];
    const float* tac   = (const float*)d_in[3];
    const float* pps   = (const float*)d_in[4];
    const float* dt    = (const float*)d_in[5];
    float* out = (float*)d_out;

    static bool attr_set = false;
    if (!attr_set) {
        cudaFuncSetAttribute(chamfer_kernel,
                             cudaFuncAttributeMaxDynamicSharedMemorySize,
                             MP * sizeof(float4));
        attr_set = true;
    }

    pose_kernel<<<1, 32>>>(state, pps, dt, out);

    const int total = FR * NV + FR * NT;   // 73728
    const int threads = 256;
    const int blocks = (total + threads - 1) / threads;   // 288
    chamfer_kernel<<<blocks, threads, MP * sizeof(float4)>>>(model, vis, tac, out);
}

// round 2
// speedup vs baseline: 2.3198x; 2.3198x over previous
#include <cuda_runtime.h>
#include <math.h>

#define FR 16
#define NV 4096
#define NT 512
#define MP 4096
#define SCALE 0.1f

#define CHUNKS 4
#define CHUNK_PTS (MP / CHUNKS)        // 1024 model points per chunk
#define CHUNK_PAIRS (CHUNK_PTS / 2)    // 512 pair records
#define P 8                            // pred points per thread
#define TPB 256
#define TILE_PTS (TPB * P)             // 2048 pred points per tile
#define TOTAL_PTS (FR * NV + FR * NT)  // 73728
#define N_TILES (TOTAL_PTS / TILE_PTS) // 36

// Per-frame fused transform: c_j = sum_k p_k * A[f][k*3+j] + B[f][j]
__device__ float g_A[FR][9];
__device__ float g_B[FR][3];
// Partial (pn + min over chunk) per chunk per pred point
__device__ float g_partial[CHUNKS][TOTAL_PTS];

typedef unsigned long long u64;

__device__ __forceinline__ u64 pack2(float a, float b) {
    u64 r;
    asm("mov.b64 %0, {%1, %2};" : "=l"(r) : "f"(a), "f"(b));
    return r;
}
__device__ __forceinline__ void unpack2(u64 v, float& a, float& b) {
    asm("mov.b64 {%0, %1}, %2;" : "=f"(a), "=f"(b) : "l"(v));
}
#define FMA2(d, a, b, c) \
    asm("fma.rn.f32x2 %0, %1, %2, %3;" : "=l"(d) : "l"(a), "l"(b), "l"(c))

__device__ __forceinline__ void rot_from_omega(const float* om, float dtv, float* R) {
    float th = sqrtf(om[0]*om[0] + om[1]*om[1] + om[2]*om[2]);
    float inv = 1.0f / fmaxf(th, 1e-8f);
    float ax = om[0]*inv, ay = om[1]*inv, az = om[2]*inv;
    float s = sinf(th * dtv);
    float c = 1.0f - cosf(th * dtv);
    float S[9] = {0.f, -az, ay,  az, 0.f, -ax,  -ay, ax, 0.f};
    float S2[9];
    for (int i = 0; i < 3; i++)
        for (int j = 0; j < 3; j++) {
            float v = 0.f;
            for (int k = 0; k < 3; k++) v += S[i*3+k] * S[k*3+j];
            S2[i*3+j] = v;
        }
    for (int i = 0; i < 9; i++) {
        float eye = (i == 0 || i == 4 || i == 8) ? 1.0f : 0.0f;
        R[i] = eye + s * S[i] + c * S2[i];
    }
}

__global__ void pose_kernel(const float* __restrict__ state,
                            const float* __restrict__ pps,
                            const float* __restrict__ dt,
                            float* __restrict__ out) {
    if (threadIdx.x != 0 || blockIdx.x != 0) return;
    out[0] = 0.0f;

    float t[3] = {state[0], state[1], state[2]};
    float r[9];
    rot_from_omega(state + 3, 1.0f, r);

    const float invS = 1.0f / SCALE;
    for (int f = 0; f < FR; f++) {
        if (f > 0) {
            const float* row = pps + f * 12;
            float d = dt[f];
            t[0] += row[6] * d;
            t[1] += row[7] * d;
            t[2] += row[8] * d;
            float Rn[9];
            rot_from_omega(row + 9, d, Rn);
            float rNew[9];
            for (int i = 0; i < 3; i++)
                for (int j = 0; j < 3; j++) {
                    float v = 0.f;
                    for (int k = 0; k < 3; k++) v += Rn[i*3+k] * r[k*3+j];
                    rNew[i*3+j] = v;
                }
            for (int i = 0; i < 9; i++) r[i] = rNew[i];
        }
        for (int i = 0; i < 9; i++) g_A[f][i] = r[i] * invS;
        for (int j = 0; j < 3; j++) {
            float v = t[0]*r[0*3+j] + t[1]*r[1*3+j] + t[2]*r[2*3+j];
            g_B[f][j] = -v * invS;
        }
    }
}

// Map global pred index -> (frame, source pointer)
__device__ __forceinline__ const float* pred_ptr(int idx, const float* vis,
                                                 const float* tac, int& f) {
    if (idx < FR * NV) {
        f = idx >> 12;
        return vis + 3 * idx;
    } else {
        int j = idx - FR * NV;
        f = j >> 9;
        return tac + 3 * j;
    }
}

__global__ void __launch_bounds__(TPB, 1)
chamfer_partial_kernel(const float* __restrict__ model,
                       const float* __restrict__ vis,
                       const float* __restrict__ tac) {
    // smem pair layout, 8 floats per 2 model points:
    // [x0,x1,y0,y1,z0,z1,n0,n1]  -> two LDS.128 via ld.shared.v2.u64
    __shared__ float s[CHUNK_PAIRS * 8];   // 16 KB

    const int tid = threadIdx.x;
    const int tile = blockIdx.x;
    const int chunk = blockIdx.y;
    const int tileBase = tile * TILE_PTS;

    // Stage this model chunk into pair-interleaved smem
    for (int j = tid; j < CHUNK_PAIRS; j += TPB) {
        int m0 = chunk * CHUNK_PTS + 2 * j;
        float x0 = model[3*m0+0], y0 = model[3*m0+1], z0 = model[3*m0+2];
        float x1 = model[3*m0+3], y1 = model[3*m0+4], z1 = model[3*m0+5];
        float* sp = s + 8 * j;
        sp[0] = x0; sp[1] = x1;
        sp[2] = y0; sp[3] = y1;
        sp[4] = z0; sp[5] = z1;
        sp[6] = x0*x0 + y0*y0 + z0*z0;
        sp[7] = x1*x1 + y1*y1 + z1*z1;
    }
    __syncthreads();

    // Per-thread pred-point setup: P points, dup-packed -2c coords
    u64 mxx[P], myy[P], mzz[P];
    float pn[P], bl[P], bh[P];
    int pidx[P];

    #pragma unroll
    for (int k = 0; k < P; k++) {
        int idx = tileBase + tid + k * TPB;
        pidx[k] = idx;
        int f;
        const float* p = pred_ptr(idx, vis, tac, f);
        float px = p[0], py = p[1], pz = p[2];
        const float* A = g_A[f];
        const float* B = g_B[f];
        float cx = fmaf(px, A[0], fmaf(py, A[3], fmaf(pz, A[6], B[0])));
        float cy = fmaf(px, A[1], fmaf(py, A[4], fmaf(pz, A[7], B[1])));
        float cz = fmaf(px, A[2], fmaf(py, A[5], fmaf(pz, A[8], B[2])));
        pn[k] = cx*cx + cy*cy + cz*cz;
        float mx = -2.0f * cx, my = -2.0f * cy, mz = -2.0f * cz;
        mxx[k] = pack2(mx, mx);
        myy[k] = pack2(my, my);
        mzz[k] = pack2(mz, mz);
        bl[k] = INFINITY;
        bh[k] = INFINITY;
    }

    unsigned sbase = (unsigned)__cvta_generic_to_shared(s);

    #pragma unroll 2
    for (int j = 0; j < CHUNK_PAIRS; j++) {
        unsigned a0 = sbase + j * 32u;
        u64 xx, yy, zz, nn;
        asm volatile("ld.shared.v2.u64 {%0, %1}, [%2];"
                     : "=l"(xx), "=l"(yy) : "r"(a0));
        asm volatile("ld.shared.v2.u64 {%0, %1}, [%2];"
                     : "=l"(zz), "=l"(nn) : "r"(a0 + 16u));
        #pragma unroll
        for (int k = 0; k < P; k++) {
            u64 acc;
            FMA2(acc, mzz[k], zz, nn);
            FMA2(acc, myy[k], yy, acc);
            FMA2(acc, mxx[k], xx, acc);
            float lo, hi;
            unpack2(acc, lo, hi);
            bl[k] = fminf(bl[k], lo);
            bh[k] = fminf(bh[k], hi);
        }
    }

    #pragma unroll
    for (int k = 0; k < P; k++) {
        float best = fminf(bl[k], bh[k]);
        g_partial[chunk][pidx[k]] = pn[k] + best;
    }
}

__global__ void __launch_bounds__(256)
final_reduce_kernel(float* __restrict__ out) {
    const int idx = blockIdx.x * blockDim.x + threadIdx.x;

    float contrib = 0.0f;
    if (idx < TOTAL_PTS) {
        float v = fminf(fminf(g_partial[0][idx], g_partial[1][idx]),
                        fminf(g_partial[2][idx], g_partial[3][idx]));
        float w = (idx < FR * NV) ? (1.0f / (float)NV) : (0.1f / (float)NT);
        contrib = v * w;
    }

    __shared__ float warp_sums[8];
    unsigned mask = 0xFFFFFFFFu;
    #pragma unroll
    for (int off = 16; off > 0; off >>= 1)
        contrib += __shfl_down_sync(mask, contrib, off);

    int lane = threadIdx.x & 31;
    int wid  = threadIdx.x >> 5;
    if (lane == 0) warp_sums[wid] = contrib;
    __syncthreads();
    if (wid == 0) {
        float v = (lane < 8) ? warp_sums[lane] : 0.0f;
        #pragma unroll
        for (int off = 4; off > 0; off >>= 1)
            v += __shfl_down_sync(mask, v, off);
        if (lane == 0) atomicAdd(out, v);
    }
}

extern "C" void kernel_launch(void* const* d_in, const int* in_sizes, int n_in,
                              void* d_out, int out_size) {
    const float* state = (const float*)d_in[0];
    const float* model = (const float*)d_in[1];
    const float* vis   = (const float*)d_in[2];
    const float* tac   = (const float*)d_in[3];
    const float* pps   = (const float*)d_in[4];
    const float* dt    = (const float*)d_in[5];
    float* out = (float*)d_out;

    pose_kernel<<<1, 32>>>(state, pps, dt, out);

    dim3 grid(N_TILES, CHUNKS);   // 36 x 4 = 144 blocks
    chamfer_partial_kernel<<<grid, TPB>>>(model, vis, tac);

    const int rblocks = (TOTAL_PTS + 255) / 256;   // 288
    final_reduce_kernel<<<rblocks, 256>>>(out);
}

// round 3
// speedup vs baseline: 2.6099x; 1.1251x over previous
#include <cuda_runtime.h>
#include <math.h>

#define FR 16
#define NV 4096
#define NT 512
#define MP 4096
#define SCALE 0.1f

#define CHUNKS 8
#define CHUNK_PTS (MP / CHUNKS)        // 512 model points per chunk
#define CHUNK_PAIRS (CHUNK_PTS / 2)    // 256 pair records
#define P 8                            // pred points per thread
#define TPB 256
#define TILE_PTS (TPB * P)             // 2048 pred points per tile
#define TOTAL_PTS (FR * NV + FR * NT)  // 73728
#define N_TILES (TOTAL_PTS / TILE_PTS) // 36

// Partial (pn + min over chunk) per chunk per pred point
__device__ float g_partial[CHUNKS][TOTAL_PTS];

typedef unsigned long long u64;

__device__ __forceinline__ u64 pack2(float a, float b) {
    u64 r;
    asm("mov.b64 %0, {%1, %2};" : "=l"(r) : "f"(a), "f"(b));
    return r;
}
#define FMA2(d, a, b, c) \
    asm("fma.rn.f32x2 %0, %1, %2, %3;" : "=l"(d) : "l"(a), "l"(b), "l"(c))

__device__ __forceinline__ void rot_from_omega(float ox, float oy, float oz,
                                               float dtv, float* R) {
    float th = sqrtf(ox*ox + oy*oy + oz*oz);
    float inv = 1.0f / fmaxf(th, 1e-8f);
    float ax = ox*inv, ay = oy*inv, az = oz*inv;
    float s = sinf(th * dtv);
    float c = 1.0f - cosf(th * dtv);
    float S[9] = {0.f, -az, ay,  az, 0.f, -ax,  -ay, ax, 0.f};
    float S2[9];
    #pragma unroll
    for (int i = 0; i < 3; i++)
        #pragma unroll
        for (int j = 0; j < 3; j++) {
            float v = 0.f;
            #pragma unroll
            for (int k = 0; k < 3; k++) v += S[i*3+k] * S[k*3+j];
            S2[i*3+j] = v;
        }
    #pragma unroll
    for (int i = 0; i < 9; i++) {
        float eye = (i == 0 || i == 4 || i == 8) ? 1.0f : 0.0f;
        R[i] = eye + s * S[i] + c * S2[i];
    }
}

// Map global pred index -> (frame, source pointer)
__device__ __forceinline__ const float* pred_ptr(int idx, const float* vis,
                                                 const float* tac, int& f) {
    if (idx < FR * NV) {
        f = idx >> 12;
        return vis + 3 * idx;
    } else {
        int j = idx - FR * NV;
        f = j >> 9;
        return tac + 3 * j;
    }
}

__global__ void __launch_bounds__(TPB, 2)
chamfer_partial_kernel(const float* __restrict__ state,
                       const float* __restrict__ pps,
                       const float* __restrict__ dt,
                       const float* __restrict__ model,
                       const float* __restrict__ vis,
                       const float* __restrict__ tac,
                       float* __restrict__ out) {
    // smem pair layout, 8 floats per 2 model points:
    // [x0,x1,y0,y1,z0,z1,n0,n1]  -> two LDS.128 via ld.shared.v2.u64
    __shared__ float s[CHUNK_PAIRS * 8];   // 8 KB
    __shared__ float sA[FR][9];            // fused transform per frame
    __shared__ float sB[FR][3];
    __shared__ float xR[FR][9];            // scan exchange buffers
    __shared__ float xT[FR][3];

    const int tid = threadIdx.x;
    const int tile = blockIdx.x;
    const int chunk = blockIdx.y;
    const int tileBase = tile * TILE_PTS;

    if (tile == 0 && chunk == 0 && tid == 0) out[0] = 0.0f;

    // ---- Stage model chunk into pair-interleaved smem (all threads) ----
    for (int j = tid; j < CHUNK_PAIRS; j += TPB) {
        int m0 = chunk * CHUNK_PTS + 2 * j;
        float x0 = model[3*m0+0], y0 = model[3*m0+1], z0 = model[3*m0+2];
        float x1 = model[3*m0+3], y1 = model[3*m0+4], z1 = model[3*m0+5];
        float* sp = s + 8 * j;
        sp[0] = x0; sp[1] = x1;
        sp[2] = y0; sp[3] = y1;
        sp[4] = z0; sp[5] = z1;
        sp[6] = x0*x0 + y0*y0 + z0*z0;
        sp[7] = x1*x1 + y1*y1 + z1*z1;
    }

    // ---- Pose computation: warp 0, thread f owns frame f ----
    if (tid < 32) {
        const int f = tid;
        float r[9];       // this frame's delta rotation (then prefix product)
        float tv[3];      // this frame's delta translation (then prefix sum)
        if (f < FR) {
            if (f == 0) {
                rot_from_omega(state[3], state[4], state[5], 1.0f, r);
                tv[0] = state[0]; tv[1] = state[1]; tv[2] = state[2];
            } else {
                const float* row = pps + f * 12;
                float d = dt[f];
                rot_from_omega(row[9], row[10], row[11], d, r);
                tv[0] = row[6] * d; tv[1] = row[7] * d; tv[2] = row[8] * d;
            }
        }
        // Hillis-Steele inclusive scan: r_f <- r_f @ r_{f-d}, t_f <- t_f + t_{f-d}
        #pragma unroll
        for (int d = 1; d < FR; d <<= 1) {
            if (f < FR) {
                #pragma unroll
                for (int i = 0; i < 9; i++) xR[f][i] = r[i];
                #pragma unroll
                for (int i = 0; i < 3; i++) xT[f][i] = tv[i];
            }
            __syncwarp();
            float pR[9], pT[3];
            if (f < FR && f >= d) {
                #pragma unroll
                for (int i = 0; i < 9; i++) pR[i] = xR[f-d][i];
                #pragma unroll
                for (int i = 0; i < 3; i++) pT[i] = xT[f-d][i];
            }
            __syncwarp();
            if (f < FR && f >= d) {
                float rn[9];
                #pragma unroll
                for (int i = 0; i < 3; i++)
                    #pragma unroll
                    for (int j = 0; j < 3; j++)
                        rn[i*3+j] = r[i*3+0]*pR[0*3+j] + r[i*3+1]*pR[1*3+j]
                                  + r[i*3+2]*pR[2*3+j];
                #pragma unroll
                for (int i = 0; i < 9; i++) r[i] = rn[i];
                #pragma unroll
                for (int i = 0; i < 3; i++) tv[i] += pT[i];
            }
        }
        // Fused transform for frame f
        if (f < FR) {
            const float invS = 1.0f / SCALE;
            #pragma unroll
            for (int i = 0; i < 9; i++) sA[f][i] = r[i] * invS;
            #pragma unroll
            for (int j = 0; j < 3; j++) {
                float v = tv[0]*r[0*3+j] + tv[1]*r[1*3+j] + tv[2]*r[2*3+j];
                sB[f][j] = -v * invS;
            }
        }
    }
    __syncthreads();

    // ---- Per-thread pred-point setup: P points, dup-packed -2c coords ----
    u64 mxx[P], myy[P], mzz[P];
    float pn[P], bl[P], bh[P];

    #pragma unroll
    for (int k = 0; k < P; k++) {
        int idx = tileBase + tid + k * TPB;
        int f;
        const float* p = pred_ptr(idx, vis, tac, f);
        float px = p[0], py = p[1], pz = p[2];
        const float* A = sA[f];
        const float* B = sB[f];
        float cx = fmaf(px, A[0], fmaf(py, A[3], fmaf(pz, A[6], B[0])));
        float cy = fmaf(px, A[1], fmaf(py, A[4], fmaf(pz, A[7], B[1])));
        float cz = fmaf(px, A[2], fmaf(py, A[5], fmaf(pz, A[8], B[2])));
        pn[k] = cx*cx + cy*cy + cz*cz;
        float mx = -2.0f * cx, my = -2.0f * cy, mz = -2.0f * cz;
        mxx[k] = pack2(mx, mx);
        myy[k] = pack2(my, my);
        mzz[k] = pack2(mz, mz);
        bl[k] = INFINITY;
        bh[k] = INFINITY;
    }

    unsigned sbase = (unsigned)__cvta_generic_to_shared(s);

    #pragma unroll 2
    for (int j = 0; j < CHUNK_PAIRS; j++) {
        unsigned a0 = sbase + j * 32u;
        u64 xx, yy, zz, nn;
        asm volatile("ld.shared.v2.u64 {%0, %1}, [%2];"
                     : "=l"(xx), "=l"(yy) : "r"(a0));
        asm volatile("ld.shared.v2.u64 {%0, %1}, [%2];"
                     : "=l"(zz), "=l"(nn) : "r"(a0 + 16u));
        #pragma unroll
        for (int k = 0; k < P; k++) {
            u64 acc;
            FMA2(acc, mzz[k], zz, nn);
            FMA2(acc, myy[k], yy, acc);
            FMA2(acc, mxx[k], xx, acc);
            float lo, hi;
            asm("mov.b64 {%0, %1}, %2;" : "=f"(lo), "=f"(hi) : "l"(acc));
            bl[k] = fminf(bl[k], lo);
            bh[k] = fminf(bh[k], hi);
        }
    }

    #pragma unroll
    for (int k = 0; k < P; k++) {
        int idx = tileBase + tid + k * TPB;
        float best = fminf(bl[k], bh[k]);
        g_partial[chunk][idx] = pn[k] + best;
    }
}

__global__ void __launch_bounds__(256)
final_reduce_kernel(float* __restrict__ out) {
    const int idx = blockIdx.x * blockDim.x + threadIdx.x;

    float contrib = 0.0f;
    if (idx < TOTAL_PTS) {
        float v = g_partial[0][idx];
        #pragma unroll
        for (int c = 1; c < CHUNKS; c++) v = fminf(v, g_partial[c][idx]);
        float w = (idx < FR * NV) ? (1.0f / (float)NV) : (0.1f / (float)NT);
        contrib = v * w;
    }

    __shared__ float warp_sums[8];
    unsigned mask = 0xFFFFFFFFu;
    #pragma unroll
    for (int off = 16; off > 0; off >>= 1)
        contrib += __shfl_down_sync(mask, contrib, off);

    int lane = threadIdx.x & 31;
    int wid  = threadIdx.x >> 5;
    if (lane == 0) warp_sums[wid] = contrib;
    __syncthreads();
    if (wid == 0) {
        float v = (lane < 8) ? warp_sums[lane] : 0.0f;
        #pragma unroll
        for (int off = 4; off > 0; off >>= 1)
            v += __shfl_down_sync(mask, v, off);
        if (lane == 0) atomicAdd(out, v);
    }
}

extern "C" void kernel_launch(void* const* d_in, const int* in_sizes, int n_in,
                              void* d_out, int out_size) {
    const float* state = (const float*)d_in[0];
    const float* model = (const float*)d_in[1];
    const float* vis   = (const float*)d_in[2];
    const float* tac   = (const float*)d_in[3];
    const float* pps   = (const float*)d_in[4];
    const float* dt    = (const float*)d_in[5];
    float* out = (float*)d_out;

    dim3 grid(N_TILES, CHUNKS);   // 36 x 8 = 288 blocks
    chamfer_partial_kernel<<<grid, TPB>>>(state, pps, dt, model, vis, tac, out);

    const int rblocks = (TOTAL_PTS + 255) / 256;   // 288
    final_reduce_kernel<<<rblocks, 256>>>(out);
}

// round 4
// speedup vs baseline: 2.6337x; 1.0091x over previous
#include <cuda_runtime.h>
#include <math.h>

#define FR 16
#define NV 4096
#define NT 512
#define MP 4096
#define SCALE 0.1f

#define CHUNKS 8
#define CHUNK_PTS (MP / CHUNKS)        // 512 model points per chunk
#define CHUNK_PAIRS (CHUNK_PTS / 2)    // 256 pair records
#define P 8                            // pred points per thread (consecutive)
#define TPB 256
#define TILE_PTS (TPB * P)             // 2048 pred points per tile
#define TOTAL_PTS (FR * NV + FR * NT)  // 73728
#define N_TILES (TOTAL_PTS / TILE_PTS) // 36

// Partial (pn + min over chunk) per chunk per pred point
__device__ float g_partial[CHUNKS][TOTAL_PTS];

typedef unsigned long long u64;

__device__ __forceinline__ u64 pack2(float a, float b) {
    u64 r;
    asm("mov.b64 %0, {%1, %2};" : "=l"(r) : "f"(a), "f"(b));
    return r;
}
__device__ __forceinline__ void unpack2(u64 v, float& a, float& b) {
    asm("mov.b64 {%0, %1}, %2;" : "=f"(a), "=f"(b) : "l"(v));
}
#define FMA2(d, a, b, c) \
    asm("fma.rn.f32x2 %0, %1, %2, %3;" : "=l"(d) : "l"(a), "l"(b), "l"(c))

__device__ __forceinline__ void rot_from_omega(float ox, float oy, float oz,
                                               float dtv, float* R) {
    float th = sqrtf(ox*ox + oy*oy + oz*oz);
    float inv = 1.0f / fmaxf(th, 1e-8f);
    float ax = ox*inv, ay = oy*inv, az = oz*inv;
    float s = sinf(th * dtv);
    float c = 1.0f - cosf(th * dtv);
    float S[9] = {0.f, -az, ay,  az, 0.f, -ax,  -ay, ax, 0.f};
    float S2[9];
    #pragma unroll
    for (int i = 0; i < 3; i++)
        #pragma unroll
        for (int j = 0; j < 3; j++) {
            float v = 0.f;
            #pragma unroll
            for (int k = 0; k < 3; k++) v += S[i*3+k] * S[k*3+j];
            S2[i*3+j] = v;
        }
    #pragma unroll
    for (int i = 0; i < 9; i++) {
        float eye = (i == 0 || i == 4 || i == 8) ? 1.0f : 0.0f;
        R[i] = eye + s * S[i] + c * S2[i];
    }
}

__global__ void __launch_bounds__(TPB, 2)
chamfer_partial_kernel(const float* __restrict__ state,
                       const float* __restrict__ pps,
                       const float* __restrict__ dt,
                       const float* __restrict__ model,
                       const float* __restrict__ vis,
                       const float* __restrict__ tac,
                       float* __restrict__ out) {
    // smem pair layout, 8 floats per 2 model points:
    // [x0,x1,y0,y1 | z0,z1,n0,n1]  -> two float4 loads
    __shared__ float s[CHUNK_PAIRS * 8];   // 8 KB
    __shared__ float sA[FR][9];            // fused transform per frame
    __shared__ float sB[FR][3];
    __shared__ float xR[FR][9];            // scan exchange buffers
    __shared__ float xT[FR][3];

    const int tid = threadIdx.x;
    const int tile = blockIdx.x;
    const int chunk = blockIdx.y;
    const int tileBase = tile * TILE_PTS;

    if (tile == 0 && chunk == 0 && tid == 0) out[0] = 0.0f;

    // ---- Stage model chunk into pair-interleaved smem ----
    for (int j = tid; j < CHUNK_PAIRS; j += TPB) {
        int m0 = chunk * CHUNK_PTS + 2 * j;
        float x0 = model[3*m0+0], y0 = model[3*m0+1], z0 = model[3*m0+2];
        float x1 = model[3*m0+3], y1 = model[3*m0+4], z1 = model[3*m0+5];
        float* sp = s + 8 * j;
        sp[0] = x0; sp[1] = x1;
        sp[2] = y0; sp[3] = y1;
        sp[4] = z0; sp[5] = z1;
        sp[6] = x0*x0 + y0*y0 + z0*z0;
        sp[7] = x1*x1 + y1*y1 + z1*z1;
    }

    // ---- Pose: warp 0, thread f owns frame f; Hillis-Steele scan ----
    if (tid < 32) {
        const int f = tid;
        float r[9], tv[3];
        if (f < FR) {
            if (f == 0) {
                rot_from_omega(state[3], state[4], state[5], 1.0f, r);
                tv[0] = state[0]; tv[1] = state[1]; tv[2] = state[2];
            } else {
                const float* row = pps + f * 12;
                float d = dt[f];
                rot_from_omega(row[9], row[10], row[11], d, r);
                tv[0] = row[6] * d; tv[1] = row[7] * d; tv[2] = row[8] * d;
            }
        }
        #pragma unroll
        for (int d = 1; d < FR; d <<= 1) {
            if (f < FR) {
                #pragma unroll
                for (int i = 0; i < 9; i++) xR[f][i] = r[i];
                #pragma unroll
                for (int i = 0; i < 3; i++) xT[f][i] = tv[i];
            }
            __syncwarp();
            float pR[9], pT[3];
            if (f < FR && f >= d) {
                #pragma unroll
                for (int i = 0; i < 9; i++) pR[i] = xR[f-d][i];
                #pragma unroll
                for (int i = 0; i < 3; i++) pT[i] = xT[f-d][i];
            }
            __syncwarp();
            if (f < FR && f >= d) {
                float rn[9];
                #pragma unroll
                for (int i = 0; i < 3; i++)
                    #pragma unroll
                    for (int j = 0; j < 3; j++)
                        rn[i*3+j] = r[i*3+0]*pR[0*3+j] + r[i*3+1]*pR[1*3+j]
                                  + r[i*3+2]*pR[2*3+j];
                #pragma unroll
                for (int i = 0; i < 9; i++) r[i] = rn[i];
                #pragma unroll
                for (int i = 0; i < 3; i++) tv[i] += pT[i];
            }
        }
        if (f < FR) {
            const float invS = 1.0f / SCALE;
            #pragma unroll
            for (int i = 0; i < 9; i++) sA[f][i] = r[i] * invS;
            #pragma unroll
            for (int j = 0; j < 3; j++) {
                float v = tv[0]*r[0*3+j] + tv[1]*r[1*3+j] + tv[2]*r[2*3+j];
                sB[f][j] = -v * invS;
            }
        }
    }
    __syncthreads();

    // ---- Per-thread setup: 8 CONSECUTIVE pred points, vectorized loads ----
    // 8-groups never cross frame/region boundaries (4096 and 512 % 8 == 0).
    const int idx0 = tileBase + tid * P;
    int f;
    const float* pbase;
    if (idx0 < FR * NV) {
        f = idx0 >> 12;
        pbase = vis + 3 * idx0;
    } else {
        int j = idx0 - FR * NV;
        f = j >> 9;
        pbase = tac + 3 * j;
    }

    float pc[24];
    {
        const float4* pv = (const float4*)pbase;   // 96B-aligned (idx0 % 8 == 0)
        #pragma unroll
        for (int i = 0; i < 6; i++) {
            float4 q = pv[i];
            pc[4*i+0] = q.x; pc[4*i+1] = q.y; pc[4*i+2] = q.z; pc[4*i+3] = q.w;
        }
    }

    u64 mxx[P], myy[P], mzz[P];
    float pn[P], bl[P], bh[P];
    {
        const float* A = sA[f];
        const float* B = sB[f];
        #pragma unroll
        for (int k = 0; k < P; k++) {
            float px = pc[3*k], py = pc[3*k+1], pz = pc[3*k+2];
            float cx = fmaf(px, A[0], fmaf(py, A[3], fmaf(pz, A[6], B[0])));
            float cy = fmaf(px, A[1], fmaf(py, A[4], fmaf(pz, A[7], B[1])));
            float cz = fmaf(px, A[2], fmaf(py, A[5], fmaf(pz, A[8], B[2])));
            pn[k] = cx*cx + cy*cy + cz*cz;
            float mx = -2.0f * cx, my = -2.0f * cy, mz = -2.0f * cz;
            mxx[k] = pack2(mx, mx);
            myy[k] = pack2(my, my);
            mzz[k] = pack2(mz, mz);
            bl[k] = INFINITY;
            bh[k] = INFINITY;
        }
    }

    // ---- Main loop: plain float4 smem loads, let ptxas pipeline ----
    const float4* sp4 = (const float4*)s;
    #pragma unroll 4
    for (int j = 0; j < CHUNK_PAIRS; j++) {
        float4 a = sp4[2*j];       // x0,x1,y0,y1
        float4 b = sp4[2*j+1];     // z0,z1,n0,n1
        u64 xx = pack2(a.x, a.y);
        u64 yy = pack2(a.z, a.w);
        u64 zz = pack2(b.x, b.y);
        u64 nn = pack2(b.z, b.w);
        #pragma unroll
        for (int k = 0; k < P; k++) {
            u64 acc;
            FMA2(acc, mzz[k], zz, nn);
            FMA2(acc, myy[k], yy, acc);
            FMA2(acc, mxx[k], xx, acc);
            float lo, hi;
            unpack2(acc, lo, hi);
            bl[k] = fminf(bl[k], lo);
            bh[k] = fminf(bh[k], hi);
        }
    }

    // ---- Epilogue: vectorized store of 8 consecutive partials ----
    float res[P];
    #pragma unroll
    for (int k = 0; k < P; k++)
        res[k] = pn[k] + fminf(bl[k], bh[k]);

    float4* dst = (float4*)&g_partial[chunk][idx0];
    dst[0] = make_float4(res[0], res[1], res[2], res[3]);
    dst[1] = make_float4(res[4], res[5], res[6], res[7]);
}

__device__ __forceinline__ float4 fmin4(float4 a, float4 b) {
    return make_float4(fminf(a.x, b.x), fminf(a.y, b.y),
                       fminf(a.z, b.z), fminf(a.w, b.w));
}

__global__ void __launch_bounds__(256)
final_reduce_kernel(float* __restrict__ out) {
    const int base = (blockIdx.x * 256 + threadIdx.x) * 8;   // 8 consecutive pts

    float4 m0 = *(const float4*)&g_partial[0][base];
    float4 m1 = *(const float4*)&g_partial[0][base + 4];
    #pragma unroll
    for (int c = 1; c < CHUNKS; c++) {
        m0 = fmin4(m0, *(const float4*)&g_partial[c][base]);
        m1 = fmin4(m1, *(const float4*)&g_partial[c][base + 4]);
    }
    float w = (base < FR * NV) ? (1.0f / (float)NV) : (0.1f / (float)NT);
    float contrib = ((m0.x + m0.y) + (m0.z + m0.w)
                   + (m1.x + m1.y) + (m1.z + m1.w)) * w;

    __shared__ float warp_sums[8];
    unsigned mask = 0xFFFFFFFFu;
    #pragma unroll
    for (int off = 16; off > 0; off >>= 1)
        contrib += __shfl_down_sync(mask, contrib, off);

    int lane = threadIdx.x & 31;
    int wid  = threadIdx.x >> 5;
    if (lane == 0) warp_sums[wid] = contrib;
    __syncthreads();
    if (wid == 0) {
        float v = (lane < 8) ? warp_sums[lane] : 0.0f;
        #pragma unroll
        for (int off = 4; off > 0; off >>= 1)
            v += __shfl_down_sync(mask, v, off);
        if (lane == 0) atomicAdd(out, v);
    }
}

extern "C" void kernel_launch(void* const* d_in, const int* in_sizes, int n_in,
                              void* d_out, int out_size) {
    const float* state = (const float*)d_in[0];
    const float* model = (const float*)d_in[1];
    const float* vis   = (const float*)d_in[2];
    const float* tac   = (const float*)d_in[3];
    const float* pps   = (const float*)d_in[4];
    const float* dt    = (const float*)d_in[5];
    float* out = (float*)d_out;

    dim3 grid(N_TILES, CHUNKS);   // 36 x 8 = 288 blocks
    chamfer_partial_kernel<<<grid, TPB>>>(state, pps, dt, model, vis, tac, out);

    final_reduce_kernel<<<TOTAL_PTS / (256 * 8), 256>>>(out);   // 36 blocks
}

// round 5
// speedup vs baseline: 2.7204x; 1.0329x over previous
#include <cuda_runtime.h>
#include <math.h>

#define FR 16
#define NV 4096
#define NT 512
#define MP 4096
#define SCALE 0.1f

#define CHUNKS 8
#define CHUNK_PTS (MP / CHUNKS)        // 512 model points per chunk
#define CHUNK_PAIRS (CHUNK_PTS / 2)    // 256 pair records
#define P 8                            // pred points per thread (consecutive)
#define TPB 512
#define TILE_PTS (TPB * P)             // 4096 pred points per tile
#define TOTAL_PTS (FR * NV + FR * NT)  // 73728
#define N_TILES (TOTAL_PTS / TILE_PTS) // 18

// Partial (pn + min over chunk) per chunk per pred point
__device__ float g_partial[CHUNKS][TOTAL_PTS];

typedef unsigned long long u64;

__device__ __forceinline__ u64 pack2(float a, float b) {
    u64 r;
    asm("mov.b64 %0, {%1, %2};" : "=l"(r) : "f"(a), "f"(b));
    return r;
}
__device__ __forceinline__ void unpack2(u64 v, float& a, float& b) {
    asm("mov.b64 {%0, %1}, %2;" : "=f"(a), "=f"(b) : "l"(v));
}
#define FMA2(d, a, b, c) \
    asm("fma.rn.f32x2 %0, %1, %2, %3;" : "=l"(d) : "l"(a), "l"(b), "l"(c))

__device__ __forceinline__ void rot_from_omega(float ox, float oy, float oz,
                                               float dtv, float* R) {
    float th = sqrtf(ox*ox + oy*oy + oz*oz);
    float inv = 1.0f / fmaxf(th, 1e-8f);
    float ax = ox*inv, ay = oy*inv, az = oz*inv;
    float s = sinf(th * dtv);
    float c = 1.0f - cosf(th * dtv);
    float S[9] = {0.f, -az, ay,  az, 0.f, -ax,  -ay, ax, 0.f};
    float S2[9];
    #pragma unroll
    for (int i = 0; i < 3; i++)
        #pragma unroll
        for (int j = 0; j < 3; j++) {
            float v = 0.f;
            #pragma unroll
            for (int k = 0; k < 3; k++) v += S[i*3+k] * S[k*3+j];
            S2[i*3+j] = v;
        }
    #pragma unroll
    for (int i = 0; i < 9; i++) {
        float eye = (i == 0 || i == 4 || i == 8) ? 1.0f : 0.0f;
        R[i] = eye + s * S[i] + c * S2[i];
    }
}

__global__ void __launch_bounds__(TPB, 1)
chamfer_partial_kernel(const float* __restrict__ state,
                       const float* __restrict__ pps,
                       const float* __restrict__ dt,
                       const float* __restrict__ model,
                       const float* __restrict__ vis,
                       const float* __restrict__ tac,
                       float* __restrict__ out) {
    // smem pair layout, 8 floats per 2 model points:
    // [x0,x1,y0,y1 | z0,z1,n0,n1]  -> two float4 loads
    __shared__ float s[CHUNK_PAIRS * 8];   // 8 KB
    __shared__ float sA[FR][9];            // fused transform per frame
    __shared__ float sB[FR][3];
    __shared__ float xR[FR][9];            // scan exchange buffers
    __shared__ float xT[FR][3];

    const int tid = threadIdx.x;
    const int tile = blockIdx.x;
    const int chunk = blockIdx.y;
    const int tileBase = tile * TILE_PTS;

    if (tile == 0 && chunk == 0 && tid == 0) out[0] = 0.0f;

    // ---- Stage model chunk into pair-interleaved smem ----
    if (tid < CHUNK_PAIRS) {
        int j = tid;
        int m0 = chunk * CHUNK_PTS + 2 * j;
        float x0 = model[3*m0+0], y0 = model[3*m0+1], z0 = model[3*m0+2];
        float x1 = model[3*m0+3], y1 = model[3*m0+4], z1 = model[3*m0+5];
        float* sp = s + 8 * j;
        sp[0] = x0; sp[1] = x1;
        sp[2] = y0; sp[3] = y1;
        sp[4] = z0; sp[5] = z1;
        sp[6] = x0*x0 + y0*y0 + z0*z0;
        sp[7] = x1*x1 + y1*y1 + z1*z1;
    }

    // ---- Pose: warp 0, thread f owns frame f; Hillis-Steele scan ----
    if (tid < 32) {
        const int f = tid;
        float r[9], tv[3];
        if (f < FR) {
            if (f == 0) {
                rot_from_omega(state[3], state[4], state[5], 1.0f, r);
                tv[0] = state[0]; tv[1] = state[1]; tv[2] = state[2];
            } else {
                const float* row = pps + f * 12;
                float d = dt[f];
                rot_from_omega(row[9], row[10], row[11], d, r);
                tv[0] = row[6] * d; tv[1] = row[7] * d; tv[2] = row[8] * d;
            }
        }
        #pragma unroll
        for (int d = 1; d < FR; d <<= 1) {
            if (f < FR) {
                #pragma unroll
                for (int i = 0; i < 9; i++) xR[f][i] = r[i];
                #pragma unroll
                for (int i = 0; i < 3; i++) xT[f][i] = tv[i];
            }
            __syncwarp();
            float pR[9], pT[3];
            if (f < FR && f >= d) {
                #pragma unroll
                for (int i = 0; i < 9; i++) pR[i] = xR[f-d][i];
                #pragma unroll
                for (int i = 0; i < 3; i++) pT[i] = xT[f-d][i];
            }
            __syncwarp();
            if (f < FR && f >= d) {
                float rn[9];
                #pragma unroll
                for (int i = 0; i < 3; i++)
                    #pragma unroll
                    for (int j = 0; j < 3; j++)
                        rn[i*3+j] = r[i*3+0]*pR[0*3+j] + r[i*3+1]*pR[1*3+j]
                                  + r[i*3+2]*pR[2*3+j];
                #pragma unroll
                for (int i = 0; i < 9; i++) r[i] = rn[i];
                #pragma unroll
                for (int i = 0; i < 3; i++) tv[i] += pT[i];
            }
        }
        if (f < FR) {
            const float invS = 1.0f / SCALE;
            #pragma unroll
            for (int i = 0; i < 9; i++) sA[f][i] = r[i] * invS;
            #pragma unroll
            for (int j = 0; j < 3; j++) {
                float v = tv[0]*r[0*3+j] + tv[1]*r[1*3+j] + tv[2]*r[2*3+j];
                sB[f][j] = -v * invS;
            }
        }
    }
    __syncthreads();

    // ---- Per-thread setup: 8 CONSECUTIVE pred points, vectorized loads ----
    const int idx0 = tileBase + tid * P;
    int f;
    const float* pbase;
    if (idx0 < FR * NV) {
        f = idx0 >> 12;
        pbase = vis + 3 * idx0;
    } else {
        int j = idx0 - FR * NV;
        f = j >> 9;
        pbase = tac + 3 * j;
    }

    float pc[24];
    {
        const float4* pv = (const float4*)pbase;   // 16B-aligned (idx0 % 8 == 0)
        #pragma unroll
        for (int i = 0; i < 6; i++) {
            float4 q = pv[i];
            pc[4*i+0] = q.x; pc[4*i+1] = q.y; pc[4*i+2] = q.z; pc[4*i+3] = q.w;
        }
    }

    u64 mxx[P], myy[P], mzz[P];
    float pn[P], bl[P], bh[P];
    {
        const float* A = sA[f];
        const float* B = sB[f];
        #pragma unroll
        for (int k = 0; k < P; k++) {
            float px = pc[3*k], py = pc[3*k+1], pz = pc[3*k+2];
            float cx = fmaf(px, A[0], fmaf(py, A[3], fmaf(pz, A[6], B[0])));
            float cy = fmaf(px, A[1], fmaf(py, A[4], fmaf(pz, A[7], B[1])));
            float cz = fmaf(px, A[2], fmaf(py, A[5], fmaf(pz, A[8], B[2])));
            pn[k] = cx*cx + cy*cy + cz*cz;
            float mx = -2.0f * cx, my = -2.0f * cy, mz = -2.0f * cz;
            mxx[k] = pack2(mx, mx);
            myy[k] = pack2(my, my);
            mzz[k] = pack2(mz, mz);
            bl[k] = INFINITY;
            bh[k] = INFINITY;
        }
    }

    // ---- Main loop ----
    const float4* sp4 = (const float4*)s;
    #pragma unroll 4
    for (int j = 0; j < CHUNK_PAIRS; j++) {
        float4 a = sp4[2*j];       // x0,x1,y0,y1
        float4 b = sp4[2*j+1];     // z0,z1,n0,n1
        u64 xx = pack2(a.x, a.y);
        u64 yy = pack2(a.z, a.w);
        u64 zz = pack2(b.x, b.y);
        u64 nn = pack2(b.z, b.w);
        #pragma unroll
        for (int k = 0; k < P; k++) {
            u64 acc;
            FMA2(acc, mzz[k], zz, nn);
            FMA2(acc, myy[k], yy, acc);
            FMA2(acc, mxx[k], xx, acc);
            float lo, hi;
            unpack2(acc, lo, hi);
            bl[k] = fminf(bl[k], lo);
            bh[k] = fminf(bh[k], hi);
        }
    }

    // ---- Epilogue: vectorized store of 8 consecutive partials ----
    float res[P];
    #pragma unroll
    for (int k = 0; k < P; k++)
        res[k] = pn[k] + fminf(bl[k], bh[k]);

    float4* dst = (float4*)&g_partial[chunk][idx0];
    dst[0] = make_float4(res[0], res[1], res[2], res[3]);
    dst[1] = make_float4(res[4], res[5], res[6], res[7]);
}

__device__ __forceinline__ float2 fmin2v(float2 a, float2 b) {
    return make_float2(fminf(a.x, b.x), fminf(a.y, b.y));
}

__global__ void __launch_bounds__(256)
final_reduce_kernel(float* __restrict__ out) {
    const int base = (blockIdx.x * 256 + threadIdx.x) * 2;   // 2 consecutive pts

    float2 m = *(const float2*)&g_partial[0][base];
    #pragma unroll
    for (int c = 1; c < CHUNKS; c++)
        m = fmin2v(m, *(const float2*)&g_partial[c][base]);

    float w = (base < FR * NV) ? (1.0f / (float)NV) : (0.1f / (float)NT);
    float contrib = (m.x + m.y) * w;

    __shared__ float warp_sums[8];
    unsigned mask = 0xFFFFFFFFu;
    #pragma unroll
    for (int off = 16; off > 0; off >>= 1)
        contrib += __shfl_down_sync(mask, contrib, off);

    int lane = threadIdx.x & 31;
    int wid  = threadIdx.x >> 5;
    if (lane == 0) warp_sums[wid] = contrib;
    __syncthreads();
    if (wid == 0) {
        float v = (lane < 8) ? warp_sums[lane] : 0.0f;
        #pragma unroll
        for (int off = 4; off > 0; off >>= 1)
            v += __shfl_down_sync(mask, v, off);
        if (lane == 0) atomicAdd(out, v);
    }
}

extern "C" void kernel_launch(void* const* d_in, const int* in_sizes, int n_in,
                              void* d_out, int out_size) {
    const float* state = (const float*)d_in[0];
    const float* model = (const float*)d_in[1];
    const float* vis   = (const float*)d_in[2];
    const float* tac   = (const float*)d_in[3];
    const float* pps   = (const float*)d_in[4];
    const float* dt    = (const float*)d_in[5];
    float* out = (float*)d_out;

    dim3 grid(N_TILES, CHUNKS);   // 18 x 8 = 144 blocks (one wave, 1 block/SM)
    chamfer_partial_kernel<<<grid, TPB>>>(state, pps, dt, model, vis, tac, out);

    final_reduce_kernel<<<TOTAL_PTS / (256 * 2), 256>>>(out);   // 144 blocks
}

// round 7
// speedup vs baseline: 2.7223x; 1.0007x over previous
#include <cuda_runtime.h>
#include <math.h>

#define FR 16
#define NV 4096
#define NT 512
#define MP 4096
#define SCALE 0.1f

#define CHUNKS 8
#define CHUNK_PTS (MP / CHUNKS)        // 512 model points per chunk
#define CHUNK_PAIRS (CHUNK_PTS / 2)    // 256 pair records
#define P 8                            // pred points per thread (consecutive)
#define TPB 512
#define TILE_PTS (TPB * P)             // 4096 pred points per tile
#define TOTAL_PTS (FR * NV + FR * NT)  // 73728
#define N_TILES (TOTAL_PTS / TILE_PTS) // 18

// Partial (pn + min over chunk) per chunk per pred point
__device__ float g_partial[CHUNKS][TOTAL_PTS];

typedef unsigned long long u64;

__device__ __forceinline__ u64 pack2(float a, float b) {
    u64 r;
    asm("mov.b64 %0, {%1, %2};" : "=l"(r) : "f"(a), "f"(b));
    return r;
}
__device__ __forceinline__ void unpack2(u64 v, float& a, float& b) {
    asm("mov.b64 {%0, %1}, %2;" : "=f"(a), "=f"(b) : "l"(v));
}
#define FMA2(d, a, b, c) \
    asm("fma.rn.f32x2 %0, %1, %2, %3;" : "=l"(d) : "l"(a), "l"(b), "l"(c))

__device__ __forceinline__ void rot_from_omega(float ox, float oy, float oz,
                                               float dtv, float* R) {
    float th = sqrtf(ox*ox + oy*oy + oz*oz);
    float inv = 1.0f / fmaxf(th, 1e-8f);
    float ax = ox*inv, ay = oy*inv, az = oz*inv;
    float s = sinf(th * dtv);
    float c = 1.0f - cosf(th * dtv);
    float S[9] = {0.f, -az, ay,  az, 0.f, -ax,  -ay, ax, 0.f};
    float S2[9];
    #pragma unroll
    for (int i = 0; i < 3; i++)
        #pragma unroll
        for (int j = 0; j < 3; j++) {
            float v = 0.f;
            #pragma unroll
            for (int k = 0; k < 3; k++) v += S[i*3+k] * S[k*3+j];
            S2[i*3+j] = v;
        }
    #pragma unroll
    for (int i = 0; i < 9; i++) {
        float eye = (i == 0 || i == 4 || i == 8) ? 1.0f : 0.0f;
        R[i] = eye + s * S[i] + c * S2[i];
    }
}

__global__ void __launch_bounds__(TPB, 1)
chamfer_partial_kernel(const float* __restrict__ state,
                       const float* __restrict__ pps,
                       const float* __restrict__ dt,
                       const float* __restrict__ model,
                       const float* __restrict__ vis,
                       const float* __restrict__ tac,
                       float* __restrict__ out) {
    // smem pair layout, 8 floats per 2 model points:
    // [x0,x1,y0,y1 | z0,z1,n0,n1]  -> two ulonglong2 (LDS.128) loads,
    // each u64 half is already an (even,odd) packed f32x2 operand.
    __shared__ __align__(16) float s[CHUNK_PAIRS * 8];   // 8 KB
    __shared__ float sA[FR][9];            // fused transform per frame
    __shared__ float sB[FR][3];
    __shared__ float xR[FR][9];            // scan exchange buffers
    __shared__ float xT[FR][3];

    const int tid = threadIdx.x;
    const int tile = blockIdx.x;
    const int chunk = blockIdx.y;
    const int tileBase = tile * TILE_PTS;

    if (tile == 0 && chunk == 0 && tid == 0) out[0] = 0.0f;

    // ---- Stage model chunk into pair-interleaved smem ----
    if (tid < CHUNK_PAIRS) {
        int j = tid;
        int m0 = chunk * CHUNK_PTS + 2 * j;
        float x0 = model[3*m0+0], y0 = model[3*m0+1], z0 = model[3*m0+2];
        float x1 = model[3*m0+3], y1 = model[3*m0+4], z1 = model[3*m0+5];
        float* sp = s + 8 * j;
        sp[0] = x0; sp[1] = x1;
        sp[2] = y0; sp[3] = y1;
        sp[4] = z0; sp[5] = z1;
        sp[6] = x0*x0 + y0*y0 + z0*z0;
        sp[7] = x1*x1 + y1*y1 + z1*z1;
    }

    // ---- Pose: warp 0, thread f owns frame f; Hillis-Steele scan ----
    if (tid < 32) {
        const int f = tid;
        float r[9], tv[3];
        if (f < FR) {
            if (f == 0) {
                rot_from_omega(state[3], state[4], state[5], 1.0f, r);
                tv[0] = state[0]; tv[1] = state[1]; tv[2] = state[2];
            } else {
                const float* row = pps + f * 12;
                float d = dt[f];
                rot_from_omega(row[9], row[10], row[11], d, r);
                tv[0] = row[6] * d; tv[1] = row[7] * d; tv[2] = row[8] * d;
            }
        }
        #pragma unroll
        for (int d = 1; d < FR; d <<= 1) {
            if (f < FR) {
                #pragma unroll
                for (int i = 0; i < 9; i++) xR[f][i] = r[i];
                #pragma unroll
                for (int i = 0; i < 3; i++) xT[f][i] = tv[i];
            }
            __syncwarp();
            float pR[9], pT[3];
            if (f < FR && f >= d) {
                #pragma unroll
                for (int i = 0; i < 9; i++) pR[i] = xR[f-d][i];
                #pragma unroll
                for (int i = 0; i < 3; i++) pT[i] = xT[f-d][i];
            }
            __syncwarp();
            if (f < FR && f >= d) {
                float rn[9];
                #pragma unroll
                for (int i = 0; i < 3; i++)
                    #pragma unroll
                    for (int j = 0; j < 3; j++)
                        rn[i*3+j] = r[i*3+0]*pR[0*3+j] + r[i*3+1]*pR[1*3+j]
                                  + r[i*3+2]*pR[2*3+j];
                #pragma unroll
                for (int i = 0; i < 9; i++) r[i] = rn[i];
                #pragma unroll
                for (int i = 0; i < 3; i++) tv[i] += pT[i];
            }
        }
        if (f < FR) {
            const float invS = 1.0f / SCALE;
            #pragma unroll
            for (int i = 0; i < 9; i++) sA[f][i] = r[i] * invS;
            #pragma unroll
            for (int j = 0; j < 3; j++) {
                float v = tv[0]*r[0*3+j] + tv[1]*r[1*3+j] + tv[2]*r[2*3+j];
                sB[f][j] = -v * invS;
            }
        }
    }
    __syncthreads();

    // ---- Per-thread setup: 8 CONSECUTIVE pred points, vectorized loads ----
    const int idx0 = tileBase + tid * P;
    int f;
    const float* pbase;
    if (idx0 < FR * NV) {
        f = idx0 >> 12;
        pbase = vis + 3 * idx0;
    } else {
        int j = idx0 - FR * NV;
        f = j >> 9;
        pbase = tac + 3 * j;
    }

    float pc[24];
    {
        const float4* pv = (const float4*)pbase;   // 16B-aligned (idx0 % 8 == 0)
        #pragma unroll
        for (int i = 0; i < 6; i++) {
            float4 q = pv[i];
            pc[4*i+0] = q.x; pc[4*i+1] = q.y; pc[4*i+2] = q.z; pc[4*i+3] = q.w;
        }
    }

    u64 mxx[P], myy[P], mzz[P];
    float pn[P], bl[P], bh[P];
    {
        const float* A = sA[f];
        const float* B = sB[f];
        #pragma unroll
        for (int k = 0; k < P; k++) {
            float px = pc[3*k], py = pc[3*k+1], pz = pc[3*k+2];
            float cx = fmaf(px, A[0], fmaf(py, A[3], fmaf(pz, A[6], B[0])));
            float cy = fmaf(px, A[1], fmaf(py, A[4], fmaf(pz, A[7], B[1])));
            float cz = fmaf(px, A[2], fmaf(py, A[5], fmaf(pz, A[8], B[2])));
            pn[k] = cx*cx + cy*cy + cz*cz;
            float mx = -2.0f * cx, my = -2.0f * cy, mz = -2.0f * cz;
            mxx[k] = pack2(mx, mx);
            myy[k] = pack2(my, my);
            mzz[k] = pack2(mz, mz);
            bl[k] = INFINITY;
            bh[k] = INFINITY;
        }
    }

    // ---- Main loop: ulonglong2 loads give pre-packed f32x2 operands ----
    const ulonglong2* sp2 = (const ulonglong2*)s;
    #pragma unroll 4
    for (int j = 0; j < CHUNK_PAIRS; j++) {
        ulonglong2 v0 = sp2[2*j];      // .x = (x0,x1)  .y = (y0,y1)
        ulonglong2 v1 = sp2[2*j+1];    // .x = (z0,z1)  .y = (n0,n1)
        #pragma unroll
        for (int k = 0; k < P; k++) {
            u64 acc;
            FMA2(acc, mzz[k], v1.x, v1.y);
            FMA2(acc, myy[k], v0.y, acc);
            FMA2(acc, mxx[k], v0.x, acc);
            float lo, hi;
            unpack2(acc, lo, hi);
            bl[k] = fminf(bl[k], lo);
            bh[k] = fminf(bh[k], hi);
        }
    }

    // ---- Epilogue: vectorized store of 8 consecutive partials ----
    float res[P];
    #pragma unroll
    for (int k = 0; k < P; k++)
        res[k] = pn[k] + fminf(bl[k], bh[k]);

    float4* dst = (float4*)&g_partial[chunk][idx0];
    dst[0] = make_float4(res[0], res[1], res[2], res[3]);
    dst[1] = make_float4(res[4], res[5], res[6], res[7]);
}

__global__ void __launch_bounds__(256)
final_reduce_kernel(float* __restrict__ out) {
    const int idx = blockIdx.x * 256 + threadIdx.x;   // one point per thread

    float m = g_partial[0][idx];
    #pragma unroll
    for (int c = 1; c < CHUNKS; c++)
        m = fminf(m, g_partial[c][idx]);

    float w = (idx < FR * NV) ? (1.0f / (float)NV) : (0.1f / (float)NT);
    float contrib = m * w;

    __shared__ float warp_sums[8];
    unsigned mask = 0xFFFFFFFFu;
    #pragma unroll
    for (int off = 16; off > 0; off >>= 1)
        contrib += __shfl_down_sync(mask, contrib, off);

    int lane = threadIdx.x & 31;
    int wid  = threadIdx.x >> 5;
    if (lane == 0) warp_sums[wid] = contrib;
    __syncthreads();
    if (wid == 0) {
        float v = (lane < 8) ? warp_sums[lane] : 0.0f;
        #pragma unroll
        for (int off = 4; off > 0; off >>= 1)
            v += __shfl_down_sync(mask, v, off);
        if (lane == 0) atomicAdd(out, v);
    }
}

extern "C" void kernel_launch(void* const* d_in, const int* in_sizes, int n_in,
                              void* d_out, int out_size) {
    const float* state = (const float*)d_in[0];
    const float* model = (const float*)d_in[1];
    const float* vis   = (const float*)d_in[2];
    const float* tac   = (const float*)d_in[3];
    const float* pps   = (const float*)d_in[4];
    const float* dt    = (const float*)d_in[5];
    float* out = (float*)d_out;

    dim3 grid(N_TILES, CHUNKS);   // 18 x 8 = 144 blocks (one wave, 1 block/SM)
    chamfer_partial_kernel<<<grid, TPB>>>(state, pps, dt, model, vis, tac, out);

    final_reduce_kernel<<<TOTAL_PTS / 256, 256>>>(out);   // 288 blocks
}